// round 2
// baseline (speedup 1.0000x reference)
#include <cuda_runtime.h>
#include <cstdint>

#define BATCH    8192
#define IN_SIZE  512
#define OUT_SIZE 512
#define GC       8
#define KDIM     (IN_SIZE * GC)   /* 4096 */

// Scratch (allocation-free rule: __device__ globals)
__device__ float g_S[(size_t)BATCH * KDIM];     // basis matrix, [M][K], tf32-rounded
__device__ float g_Bt[(size_t)KDIM * OUT_SIZE]; // (coeff*w) transposed, [K][N], tf32-rounded

__device__ __forceinline__ float tf32r(float f) {
    uint32_t u;
    asm("cvt.rna.tf32.f32 %0, %1;" : "=r"(u) : "f"(f));
    return __uint_as_float(u);
}

// ---------------------------------------------------------------------------
// Kernel 1: fold coefficients*weights into B operand, transposed [K][N]
// ---------------------------------------------------------------------------
__global__ void fold_kernel(const float* __restrict__ w,
                            const float* __restrict__ coef) {
    int idx = blockIdx.x * blockDim.x + threadIdx.x;   // k*512 + o
    int o = idx & (OUT_SIZE - 1);
    int k = idx >> 9;
    float v = coef[(size_t)o * KDIM + k] * w[o * IN_SIZE + (k >> 3)];
    g_Bt[idx] = tf32r(v);
}

// ---------------------------------------------------------------------------
// Kernel 2: De Boor cubic B-spline basis, 8 values per (b,i)
// ---------------------------------------------------------------------------
__global__ void basis_kernel(const float* __restrict__ x) {
    int idx = blockIdx.x * blockDim.x + threadIdx.x;   // b*512 + i
    float xe = fminf(fmaxf(x[idx], -1.0f), 1.0f);

    const float start = -1.0f;
    const float stop  = 2.142857142857143f;            // 1 + 2*4/7 (rounds to f32)
    const float step  = (stop - start) / 11.0f;

    float c[12];
#pragma unroll
    for (int k = 0; k < 12; k++) c[k] = start + (float)k * step;

    float b[11];
#pragma unroll
    for (int m = 0; m < 11; m++)
        b[m] = (xe >= c[m] && xe < c[m + 1]) ? 1.0f : 0.0f;

#pragma unroll
    for (int k = 1; k <= 3; k++) {
        float inv = 1.0f / ((float)k * step);          // uniform knots
#pragma unroll
        for (int m = 0; m < 11 - k; m++)
            b[m] = ((xe - c[m]) * b[m] + (c[m + k + 1] - xe) * b[m + 1]) * inv;
    }

    float4 v0 = make_float4(tf32r(b[0]), tf32r(b[1]), tf32r(b[2]), tf32r(b[3]));
    float4 v1 = make_float4(tf32r(b[4]), tf32r(b[5]), tf32r(b[6]), tf32r(b[7]));
    float4* dst = (float4*)(g_S + (size_t)idx * 8);
    dst[0] = v0;
    dst[1] = v1;
}

// ---------------------------------------------------------------------------
// Kernel 3: GEMM  out[8192,512] = S[8192,4096] @ Bt[4096,512]
// tf32 mma.sync m16n8k8, fp32 accumulate.
// CTA tile 128x128x32, 8 warps (4 in M x 2 in N), warp tile 32x64.
// ---------------------------------------------------------------------------
#define BM 128
#define BN 128
#define BK 32
#define SAS 129   /* A smem row stride (k-major [BK][BM], padded) */
#define SBS 136   /* B smem row stride (k-major [BK][BN], padded) */

__global__ void __launch_bounds__(256, 1)
gemm_kernel(float* __restrict__ out) {
    __shared__ __align__(16) float As[BK * SAS];   // 16.1 KB
    __shared__ __align__(16) float Bs[BK * SBS];   // 17.0 KB

    int tid  = threadIdx.x;
    int warp = tid >> 5, lane = tid & 31;
    int wm = warp & 3, wn = warp >> 2;
    int gid = lane >> 2, tig = lane & 3;

    int m0 = blockIdx.y * BM;
    int n0 = blockIdx.x * BN;

    // loader coordinates
    int mA  = tid >> 1;   // 0..127 (A row)
    int kv0 = tid & 1;    // A float4 index along k
    int kB  = tid >> 3;   // 0..31 (B k-row)
    int nv0 = tid & 7;    // B float4 index along n

    const float* Ag = g_S  + (size_t)(m0 + mA) * KDIM;
    const float* Bg = g_Bt + (size_t)kB * OUT_SIZE + n0;

    float acc[2][8][4];
#pragma unroll
    for (int i = 0; i < 2; i++)
#pragma unroll
        for (int j = 0; j < 8; j++)
#pragma unroll
            for (int l = 0; l < 4; l++) acc[i][j][l] = 0.0f;

    float4 aReg[4], bReg[4];

    // preload tile 0 into registers
#pragma unroll
    for (int it = 0; it < 4; it++) {
        aReg[it] = *(const float4*)(Ag + 4 * (kv0 + 2 * it));
        bReg[it] = *(const float4*)(Bg + 4 * (nv0 + 8 * it));
    }

    const int KT = KDIM / BK;   // 128
    for (int kt = 0; kt < KT; kt++) {
        // commit staged tile to smem (A transposed to k-major)
#pragma unroll
        for (int it = 0; it < 4; it++) {
            int kk = 4 * (kv0 + 2 * it);
            As[(kk + 0) * SAS + mA] = aReg[it].x;
            As[(kk + 1) * SAS + mA] = aReg[it].y;
            As[(kk + 2) * SAS + mA] = aReg[it].z;
            As[(kk + 3) * SAS + mA] = aReg[it].w;
            *(float4*)(Bs + kB * SBS + 4 * (nv0 + 8 * it)) = bReg[it];
        }
        __syncthreads();

        // prefetch next tile (LDG latency overlaps the MMAs below)
        if (kt + 1 < KT) {
            int koff = (kt + 1) * BK;
#pragma unroll
            for (int it = 0; it < 4; it++) {
                aReg[it] = *(const float4*)(Ag + koff + 4 * (kv0 + 2 * it));
                bReg[it] = *(const float4*)(Bg + (size_t)koff * OUT_SIZE +
                                            4 * (nv0 + 8 * it));
            }
        }

#pragma unroll
        for (int ks = 0; ks < 4; ks++) {
            int k = ks * 8;
            uint32_t af[2][4];
            uint32_t bf[8][2];
#pragma unroll
            for (int mf = 0; mf < 2; mf++) {
                int m = wm * 32 + mf * 16 + gid;
                af[mf][0] = __float_as_uint(As[(k + tig) * SAS + m]);
                af[mf][1] = __float_as_uint(As[(k + tig) * SAS + m + 8]);
                af[mf][2] = __float_as_uint(As[(k + tig + 4) * SAS + m]);
                af[mf][3] = __float_as_uint(As[(k + tig + 4) * SAS + m + 8]);
            }
#pragma unroll
            for (int nf = 0; nf < 8; nf++) {
                int n = wn * 64 + nf * 8 + gid;
                bf[nf][0] = __float_as_uint(Bs[(k + tig) * SBS + n]);
                bf[nf][1] = __float_as_uint(Bs[(k + tig + 4) * SBS + n]);
            }
#pragma unroll
            for (int mf = 0; mf < 2; mf++)
#pragma unroll
                for (int nf = 0; nf < 8; nf++)
                    asm volatile(
                        "mma.sync.aligned.m16n8k8.row.col.f32.tf32.tf32.f32 "
                        "{%0,%1,%2,%3}, {%4,%5,%6,%7}, {%8,%9}, {%0,%1,%2,%3};\n"
                        : "+f"(acc[mf][nf][0]), "+f"(acc[mf][nf][1]),
                          "+f"(acc[mf][nf][2]), "+f"(acc[mf][nf][3])
                        : "r"(af[mf][0]), "r"(af[mf][1]),
                          "r"(af[mf][2]), "r"(af[mf][3]),
                          "r"(bf[nf][0]), "r"(bf[nf][1]));
        }
        __syncthreads();
    }

    // epilogue: D fragment layout c0=(g,2t) c1=(g,2t+1) c2=(g+8,2t) c3=(g+8,2t+1)
#pragma unroll
    for (int mf = 0; mf < 2; mf++) {
        int m = m0 + wm * 32 + mf * 16 + gid;
#pragma unroll
        for (int nf = 0; nf < 8; nf++) {
            int n = n0 + wn * 64 + nf * 8 + tig * 2;
            *(float2*)(out + (size_t)m * OUT_SIZE + n) =
                make_float2(acc[mf][nf][0], acc[mf][nf][1]);
            *(float2*)(out + (size_t)(m + 8) * OUT_SIZE + n) =
                make_float2(acc[mf][nf][2], acc[mf][nf][3]);
        }
    }
}

// ---------------------------------------------------------------------------
extern "C" void kernel_launch(void* const* d_in, const int* in_sizes, int n_in,
                              void* d_out, int out_size) {
    const float* x    = (const float*)d_in[0];
    const float* w    = (const float*)d_in[1];
    const float* coef = (const float*)d_in[2];
    float* out = (float*)d_out;

    fold_kernel<<<(KDIM * OUT_SIZE) / 256, 256>>>(w, coef);
    basis_kernel<<<(BATCH * IN_SIZE) / 256, 256>>>(x);
    gemm_kernel<<<dim3(OUT_SIZE / BN, BATCH / BM), 256>>>(out);
}

// round 3
// speedup vs baseline: 2.7357x; 2.7357x over previous
#include <cuda_runtime.h>
#include <cuda_fp16.h>
#include <cstdint>

#define BATCH    8192
#define IN_SIZE  512
#define OUT_SIZE 512
#define KDIM     4096

// Scratch (__device__ globals per allocation rules)
__device__ __half g_Sh[(size_t)BATCH * KDIM];     // basis, [M][K] row-major, fp16
__device__ __half g_Bh[(size_t)OUT_SIZE * KDIM];  // coeff*w, [N][K] row-major, fp16

// ---------------------------------------------------------------------------
// Kernel 1: fold coeff*weight -> fp16, [N][K] (k-contiguous, no transpose)
// one thread per (o,i): 8 elements, 16B store
// ---------------------------------------------------------------------------
__global__ void fold_kernel(const float* __restrict__ w,
                            const float* __restrict__ coef) {
    int idx = blockIdx.x * blockDim.x + threadIdx.x;   // o*512 + i
    float wv = w[idx];
    const float4* c = (const float4*)(coef + (size_t)idx * 8);
    float4 c0 = c[0], c1 = c[1];
    __half2 h[4];
    h[0] = __floats2half2_rn(c0.x * wv, c0.y * wv);
    h[1] = __floats2half2_rn(c0.z * wv, c0.w * wv);
    h[2] = __floats2half2_rn(c1.x * wv, c1.y * wv);
    h[3] = __floats2half2_rn(c1.z * wv, c1.w * wv);
    *(uint4*)(g_Bh + (size_t)idx * 8) = *(uint4*)h;
}

// ---------------------------------------------------------------------------
// Kernel 2: De Boor cubic B-spline basis -> fp16 (8 values, one 16B store)
// ---------------------------------------------------------------------------
__global__ void basis_kernel(const float* __restrict__ x) {
    int idx = blockIdx.x * blockDim.x + threadIdx.x;   // b*512 + i
    float xe = fminf(fmaxf(x[idx], -1.0f), 1.0f);

    const float start = -1.0f;
    const float stop  = 2.142857142857143f;
    const float step  = (stop - start) / 11.0f;

    float c[12];
#pragma unroll
    for (int k = 0; k < 12; k++) c[k] = start + (float)k * step;

    float b[11];
#pragma unroll
    for (int m = 0; m < 11; m++)
        b[m] = (xe >= c[m] && xe < c[m + 1]) ? 1.0f : 0.0f;

#pragma unroll
    for (int k = 1; k <= 3; k++) {
        float inv = 1.0f / ((float)k * step);
#pragma unroll
        for (int m = 0; m < 11 - k; m++)
            b[m] = ((xe - c[m]) * b[m] + (c[m + k + 1] - xe) * b[m + 1]) * inv;
    }

    __half2 h[4];
    h[0] = __floats2half2_rn(b[0], b[1]);
    h[1] = __floats2half2_rn(b[2], b[3]);
    h[2] = __floats2half2_rn(b[4], b[5]);
    h[3] = __floats2half2_rn(b[6], b[7]);
    *(uint4*)(g_Sh + (size_t)idx * 8) = *(uint4*)h;
}

// ---------------------------------------------------------------------------
// Kernel 3: GEMM out[8192,512] = S[8192,4096] @ Bh[512,4096]^T
// fp16 mma m16n8k16, fp32 accum. CTA 128x128x32, 8 warps (4M x 2N),
// warp tile 32x64. cp.async double buffer + ldmatrix.x4.
// smem row stride 40 half (80B): bank granule (5r+s)%8 is a permutation
// over 8 rows -> conflict-free LDSM.
// ---------------------------------------------------------------------------
#define BM  128
#define BN  128
#define BK  32
#define AST 40

#define CP16(dst, src) \
    asm volatile("cp.async.cg.shared.global [%0], [%1], 16;\n" \
                 :: "r"(dst), "l"(src))

__device__ __forceinline__ void ldsm4(uint32_t& r0, uint32_t& r1,
                                      uint32_t& r2, uint32_t& r3,
                                      uint32_t addr) {
    asm volatile("ldmatrix.sync.aligned.m8n8.x4.shared.b16 {%0,%1,%2,%3}, [%4];\n"
                 : "=r"(r0), "=r"(r1), "=r"(r2), "=r"(r3) : "r"(addr));
}

__global__ void __launch_bounds__(256, 2)
gemm_kernel(float* __restrict__ out) {
    __shared__ __align__(16) __half As[2][BM * AST];   // 2 x 10 KB
    __shared__ __align__(16) __half Bs[2][BN * AST];   // 2 x 10 KB

    int tid  = threadIdx.x;
    int warp = tid >> 5, lane = tid & 31;
    int wm = warp & 3, wn = warp >> 2;
    int m0 = blockIdx.y * BM;
    int n0 = blockIdx.x * BN;

    // loader coords: 512 A-chunks + 512 B-chunks of 16B, 4 per thread
    int lrowA = tid >> 2;          // rows 0..63 for c=0, +64 for c=1
    int lseg  = tid & 3;

    float acc[2][8][4];
#pragma unroll
    for (int i = 0; i < 2; i++)
#pragma unroll
        for (int j = 0; j < 8; j++)
#pragma unroll
            for (int l = 0; l < 4; l++) acc[i][j][l] = 0.0f;

    // ---- stage loader ----
    auto load_stage = [&](int buf, int kt) {
        int koff = kt * BK;
#pragma unroll
        for (int c = 0; c < 2; c++) {
            int row = lrowA + c * 64;
            const __half* src = g_Sh + (size_t)(m0 + row) * KDIM + koff + lseg * 8;
            uint32_t dst = (uint32_t)__cvta_generic_to_shared(
                &As[buf][row * AST + lseg * 8]);
            CP16(dst, src);
        }
#pragma unroll
        for (int c = 0; c < 2; c++) {
            int row = lrowA + c * 64;
            const __half* src = g_Bh + (size_t)(n0 + row) * KDIM + koff + lseg * 8;
            uint32_t dst = (uint32_t)__cvta_generic_to_shared(
                &Bs[buf][row * AST + lseg * 8]);
            CP16(dst, src);
        }
    };

    load_stage(0, 0);
    asm volatile("cp.async.commit_group;\n");

    const int KT = KDIM / BK;   // 128
    int lr = lane & 15;
    int lh = lane >> 4;

    for (int kt = 0; kt < KT; kt++) {
        if (kt + 1 < KT) {
            load_stage((kt + 1) & 1, kt + 1);
            asm volatile("cp.async.commit_group;\n");
            asm volatile("cp.async.wait_group 1;\n");
        } else {
            asm volatile("cp.async.wait_group 0;\n");
        }
        __syncthreads();

        int buf = kt & 1;
#pragma unroll
        for (int ks = 0; ks < 2; ks++) {
            int seg = ks * 2 + lh;               // k 16B-segment for this lane
            uint32_t a[2][4], b[4][4];
#pragma unroll
            for (int mf = 0; mf < 2; mf++) {
                uint32_t addr = (uint32_t)__cvta_generic_to_shared(
                    &As[buf][(wm * 32 + mf * 16 + lr) * AST + seg * 8]);
                ldsm4(a[mf][0], a[mf][1], a[mf][2], a[mf][3], addr);
            }
#pragma unroll
            for (int p = 0; p < 4; p++) {
                uint32_t addr = (uint32_t)__cvta_generic_to_shared(
                    &Bs[buf][(wn * 64 + p * 16 + lr) * AST + seg * 8]);
                ldsm4(b[p][0], b[p][1], b[p][2], b[p][3], addr);
            }
#pragma unroll
            for (int mf = 0; mf < 2; mf++)
#pragma unroll
                for (int nf = 0; nf < 8; nf++) {
                    int p = nf >> 1, hi = nf & 1;
                    uint32_t b0 = hi ? b[p][1] : b[p][0];
                    uint32_t b1 = hi ? b[p][3] : b[p][2];
                    asm volatile(
                        "mma.sync.aligned.m16n8k16.row.col.f32.f16.f16.f32 "
                        "{%0,%1,%2,%3}, {%4,%5,%6,%7}, {%8,%9}, {%0,%1,%2,%3};\n"
                        : "+f"(acc[mf][nf][0]), "+f"(acc[mf][nf][1]),
                          "+f"(acc[mf][nf][2]), "+f"(acc[mf][nf][3])
                        : "r"(a[mf][0]), "r"(a[mf][1]),
                          "r"(a[mf][2]), "r"(a[mf][3]),
                          "r"(b0), "r"(b1));
                }
        }
        __syncthreads();
    }

    // epilogue: c0=(m,2t) c1=(m,2t+1) c2=(m+8,2t) c3=(m+8,2t+1)
    int gid = lane >> 2, tig = lane & 3;
#pragma unroll
    for (int mf = 0; mf < 2; mf++) {
        int m = m0 + wm * 32 + mf * 16 + gid;
#pragma unroll
        for (int nf = 0; nf < 8; nf++) {
            int n = n0 + wn * 64 + nf * 8 + tig * 2;
            *(float2*)(out + (size_t)m * OUT_SIZE + n) =
                make_float2(acc[mf][nf][0], acc[mf][nf][1]);
            *(float2*)(out + (size_t)(m + 8) * OUT_SIZE + n) =
                make_float2(acc[mf][nf][2], acc[mf][nf][3]);
        }
    }
}

// ---------------------------------------------------------------------------
extern "C" void kernel_launch(void* const* d_in, const int* in_sizes, int n_in,
                              void* d_out, int out_size) {
    const float* x    = (const float*)d_in[0];
    const float* w    = (const float*)d_in[1];
    const float* coef = (const float*)d_in[2];
    float* out = (float*)d_out;

    fold_kernel<<<(OUT_SIZE * IN_SIZE) / 256, 256>>>(w, coef);
    basis_kernel<<<(BATCH * IN_SIZE) / 256, 256>>>(x);
    gemm_kernel<<<dim3(OUT_SIZE / BN, BATCH / BM), 256>>>(out);
}

// round 10
// speedup vs baseline: 3.3498x; 1.2245x over previous
#include <cuda_runtime.h>
#include <cuda_fp16.h>
#include <cstdint>

#define BATCH    8192
#define IN_SIZE  512
#define OUT_SIZE 512
#define KDIM     4096

// Scratch (__device__ globals per allocation rules)
__device__ __half g_Sh[(size_t)BATCH * KDIM];     // basis, [M][K] row-major, fp16
__device__ __half g_Bh[(size_t)OUT_SIZE * KDIM];  // coeff*w, [N][K] row-major, fp16

// ---------------------------------------------------------------------------
// Kernel 1: fold coeff*weight -> fp16, [N][K]
// ---------------------------------------------------------------------------
__global__ void fold_kernel(const float* __restrict__ w,
                            const float* __restrict__ coef) {
    int idx = blockIdx.x * blockDim.x + threadIdx.x;   // o*512 + i
    float wv = w[idx];
    const float4* c = (const float4*)(coef + (size_t)idx * 8);
    float4 c0 = c[0], c1 = c[1];
    __half2 h[4];
    h[0] = __floats2half2_rn(c0.x * wv, c0.y * wv);
    h[1] = __floats2half2_rn(c0.z * wv, c0.w * wv);
    h[2] = __floats2half2_rn(c1.x * wv, c1.y * wv);
    h[3] = __floats2half2_rn(c1.z * wv, c1.w * wv);
    *(uint4*)(g_Bh + (size_t)idx * 8) = *(uint4*)h;
}

// ---------------------------------------------------------------------------
// Kernel 2: De Boor cubic B-spline basis -> fp16
// ---------------------------------------------------------------------------
__global__ void basis_kernel(const float* __restrict__ x) {
    int idx = blockIdx.x * blockDim.x + threadIdx.x;   // b*512 + i
    float xe = fminf(fmaxf(x[idx], -1.0f), 1.0f);

    const float start = -1.0f;
    const float stop  = 2.142857142857143f;
    const float step  = (stop - start) / 11.0f;

    float c[12];
#pragma unroll
    for (int k = 0; k < 12; k++) c[k] = start + (float)k * step;

    float b[11];
#pragma unroll
    for (int m = 0; m < 11; m++)
        b[m] = (xe >= c[m] && xe < c[m + 1]) ? 1.0f : 0.0f;

#pragma unroll
    for (int k = 1; k <= 3; k++) {
        float inv = 1.0f / ((float)k * step);
#pragma unroll
        for (int m = 0; m < 11 - k; m++)
            b[m] = ((xe - c[m]) * b[m] + (c[m + k + 1] - xe) * b[m + 1]) * inv;
    }

    __half2 h[4];
    h[0] = __floats2half2_rn(b[0], b[1]);
    h[1] = __floats2half2_rn(b[2], b[3]);
    h[2] = __floats2half2_rn(b[4], b[5]);
    h[3] = __floats2half2_rn(b[6], b[7]);
    *(uint4*)(g_Sh + (size_t)idx * 8) = *(uint4*)h;
}

// ---------------------------------------------------------------------------
// Kernel 3: GEMM out[8192,512] = S[8192,4096] @ Bh[512,4096]^T
// fp16 mma m16n8k16, fp32 accum.
// CTA tile 128x256, BK=64, 8 warps (2M x 4N), warp tile 64x64.
// 3-stage cp.async ring, SW128 swizzle (128B rows), 1 syncthreads/iter.
// Grid = 2 x 64 = 128 CTAs = one wave.
// ---------------------------------------------------------------------------
#define BM   128
#define BN   256
#define BK   64
#define NS   3
#define KT   (KDIM / BK)            /* 64 */
#define ASTG (BM * 128)             /* 16384 B */
#define BSTG (BN * 128)             /* 32768 B */
#define STG  (ASTG + BSTG)          /* 49152 B */

#define CP16(dst, src) \
    asm volatile("cp.async.cg.shared.global [%0], [%1], 16;\n" \
                 :: "r"(dst), "l"(src))

#define SWZ(o) ((o) ^ (((o) >> 3) & 0x70))

__device__ __forceinline__ void ldsm4(uint32_t& r0, uint32_t& r1,
                                      uint32_t& r2, uint32_t& r3,
                                      uint32_t addr) {
    asm volatile("ldmatrix.sync.aligned.m8n8.x4.shared.b16 {%0,%1,%2,%3}, [%4];\n"
                 : "=r"(r0), "=r"(r1), "=r"(r2), "=r"(r3) : "r"(addr));
}

__global__ void __launch_bounds__(256, 1)
gemm_kernel(float* __restrict__ out) {
    extern __shared__ __align__(1024) char smem[];

    const int tid  = threadIdx.x;
    const int warp = tid >> 5, lane = tid & 31;
    const int wn  = warp & 3;          // 4 N-warps
    const int wm2 = warp >> 2;         // 2 M-warps
    const int m0 = blockIdx.y * BM;
    const int n0 = blockIdx.x * BN;
    const uint32_t smem_base = (uint32_t)__cvta_generic_to_shared(smem);

    const int lr = lane & 15;
    const int lh = lane >> 4;

    float acc[4][8][4];
#pragma unroll
    for (int i = 0; i < 4; i++)
#pragma unroll
        for (int j = 0; j < 8; j++)
#pragma unroll
            for (int l = 0; l < 4; l++) acc[i][j][l] = 0.0f;

    // ---- stage loader: 16B cp.async chunks into SW128 smem ----
    auto load_stage = [&](int kt) {
        int slot = kt % NS;
        uint32_t sA = smem_base + slot * STG;
        uint32_t sB = sA + ASTG;
        int koff = kt * BK;
        // A: 128 rows x 8 segs = 1024 chunks, 4/thread
#pragma unroll
        for (int i = 0; i < 4; i++) {
            int idx = tid + i * 256;
            int row = idx >> 3, seg = idx & 7;
            const __half* src = g_Sh + (size_t)(m0 + row) * KDIM + koff + seg * 8;
            uint32_t off = row * 128 + seg * 16;
            CP16(sA + SWZ(off), src);
        }
        // B: 256 rows x 8 segs = 2048 chunks, 8/thread
#pragma unroll
        for (int i = 0; i < 8; i++) {
            int idx = tid + i * 256;
            int row = idx >> 3, seg = idx & 7;
            const __half* src = g_Bh + (size_t)(n0 + row) * KDIM + koff + seg * 8;
            uint32_t off = row * 128 + seg * 16;
            CP16(sB + SWZ(off), src);
        }
    };

    // prologue: stages 0..NS-2
#pragma unroll
    for (int s = 0; s < NS - 1; s++) {
        load_stage(s);
        asm volatile("cp.async.commit_group;" ::: "memory");
    }

    for (int kt = 0; kt < KT; kt++) {
        if (kt == KT - 1) asm volatile("cp.async.wait_group 0;" ::: "memory");
        else              asm volatile("cp.async.wait_group 1;" ::: "memory");
        __syncthreads();

        if (kt + NS - 1 < KT) {
            load_stage(kt + NS - 1);
            asm volatile("cp.async.commit_group;" ::: "memory");
        }

        int slot = kt % NS;
        uint32_t sA = smem_base + slot * STG;
        uint32_t sB = sA + ASTG;

#pragma unroll
        for (int ks = 0; ks < 4; ks++) {
            uint32_t a[4][4], b[4][4];
#pragma unroll
            for (int mf = 0; mf < 4; mf++) {
                int row = wm2 * 64 + mf * 16 + lr;
                uint32_t off = row * 128 + ks * 32 + lh * 16;
                ldsm4(a[mf][0], a[mf][1], a[mf][2], a[mf][3], sA + SWZ(off));
            }
#pragma unroll
            for (int p = 0; p < 4; p++) {
                int row = wn * 64 + p * 16 + lr;
                uint32_t off = row * 128 + ks * 32 + lh * 16;
                ldsm4(b[p][0], b[p][1], b[p][2], b[p][3], sB + SWZ(off));
            }
#pragma unroll
            for (int mf = 0; mf < 4; mf++)
#pragma unroll
                for (int nf = 0; nf < 8; nf++) {
                    int p = nf >> 1, hi = nf & 1;
                    uint32_t b0 = hi ? b[p][1] : b[p][0];
                    uint32_t b1 = hi ? b[p][3] : b[p][2];
                    asm volatile(
                        "mma.sync.aligned.m16n8k16.row.col.f32.f16.f16.f32 "
                        "{%0,%1,%2,%3}, {%4,%5,%6,%7}, {%8,%9}, {%0,%1,%2,%3};\n"
                        : "+f"(acc[mf][nf][0]), "+f"(acc[mf][nf][1]),
                          "+f"(acc[mf][nf][2]), "+f"(acc[mf][nf][3])
                        : "r"(a[mf][0]), "r"(a[mf][1]),
                          "r"(a[mf][2]), "r"(a[mf][3]),
                          "r"(b0), "r"(b1));
                }
        }
    }

    // epilogue: c0=(m,2t) c1=(m,2t+1) c2=(m+8,2t) c3=(m+8,2t+1)
    int gid = lane >> 2, tig = lane & 3;
#pragma unroll
    for (int mf = 0; mf < 4; mf++) {
        int m = m0 + wm2 * 64 + mf * 16 + gid;
#pragma unroll
        for (int nf = 0; nf < 8; nf++) {
            int n = n0 + wn * 64 + nf * 8 + tig * 2;
            *(float2*)(out + (size_t)m * OUT_SIZE + n) =
                make_float2(acc[mf][nf][0], acc[mf][nf][1]);
            *(float2*)(out + (size_t)(m + 8) * OUT_SIZE + n) =
                make_float2(acc[mf][nf][2], acc[mf][nf][3]);
        }
    }
}

// ---------------------------------------------------------------------------
extern "C" void kernel_launch(void* const* d_in, const int* in_sizes, int n_in,
                              void* d_out, int out_size) {
    const float* x    = (const float*)d_in[0];
    const float* w    = (const float*)d_in[1];
    const float* coef = (const float*)d_in[2];
    float* out = (float*)d_out;

    cudaFuncSetAttribute(gemm_kernel,
                         cudaFuncAttributeMaxDynamicSharedMemorySize,
                         NS * STG);

    fold_kernel<<<(OUT_SIZE * IN_SIZE) / 256, 256>>>(w, coef);
    basis_kernel<<<(BATCH * IN_SIZE) / 256, 256>>>(x);
    gemm_kernel<<<dim3(OUT_SIZE / BN, BATCH / BM), 256, NS * STG>>>(out);
}

// round 14
// speedup vs baseline: 3.3847x; 1.0104x over previous
#include <cuda_runtime.h>
#include <cuda_fp16.h>
#include <cstdint>

#define BATCH    8192
#define IN_SIZE  512
#define OUT_SIZE 512
#define KDIM     4096

// Scratch (__device__ globals per allocation rules)
__device__ __half g_Sh[(size_t)BATCH * KDIM];     // basis, [M][K] row-major, fp16
__device__ __half g_Bh[(size_t)OUT_SIZE * KDIM];  // coeff*w, [N][K] row-major, fp16

#define FOLD_BLOCKS 1024                           /* 512*512/256 */
#define BASIS_BLOCKS 16384                         /* 8192*512/256 */

// ---------------------------------------------------------------------------
// Kernel 1: merged prep — fold (blocks [0,1024)) + basis (blocks [1024,...))
// ---------------------------------------------------------------------------
__global__ void prep_kernel(const float* __restrict__ x,
                            const float* __restrict__ w,
                            const float* __restrict__ coef) {
    if (blockIdx.x < FOLD_BLOCKS) {
        // fold: coeff*weight -> fp16, [N][K]
        int idx = blockIdx.x * blockDim.x + threadIdx.x;   // o*512 + i
        float wv = w[idx];
        const float4* c = (const float4*)(coef + (size_t)idx * 8);
        float4 c0 = c[0], c1 = c[1];
        __half2 h[4];
        h[0] = __floats2half2_rn(c0.x * wv, c0.y * wv);
        h[1] = __floats2half2_rn(c0.z * wv, c0.w * wv);
        h[2] = __floats2half2_rn(c1.x * wv, c1.y * wv);
        h[3] = __floats2half2_rn(c1.z * wv, c1.w * wv);
        *(uint4*)(g_Bh + (size_t)idx * 8) = *(uint4*)h;
    } else {
        // basis: De Boor cubic B-spline -> fp16
        int idx = (blockIdx.x - FOLD_BLOCKS) * blockDim.x + threadIdx.x;
        float xe = fminf(fmaxf(x[idx], -1.0f), 1.0f);

        const float start = -1.0f;
        const float stop  = 2.142857142857143f;
        const float step  = (stop - start) / 11.0f;

        float c[12];
#pragma unroll
        for (int k = 0; k < 12; k++) c[k] = start + (float)k * step;

        float b[11];
#pragma unroll
        for (int m = 0; m < 11; m++)
            b[m] = (xe >= c[m] && xe < c[m + 1]) ? 1.0f : 0.0f;

#pragma unroll
        for (int k = 1; k <= 3; k++) {
            float inv = 1.0f / ((float)k * step);
#pragma unroll
            for (int m = 0; m < 11 - k; m++)
                b[m] = ((xe - c[m]) * b[m] + (c[m + k + 1] - xe) * b[m + 1]) * inv;
        }

        __half2 h[4];
        h[0] = __floats2half2_rn(b[0], b[1]);
        h[1] = __floats2half2_rn(b[2], b[3]);
        h[2] = __floats2half2_rn(b[4], b[5]);
        h[3] = __floats2half2_rn(b[6], b[7]);
        *(uint4*)(g_Sh + (size_t)idx * 8) = *(uint4*)h;
    }
}

// ---------------------------------------------------------------------------
// Kernel 2: GEMM out[8192,512] = S[8192,4096] @ Bh[512,4096]^T
// fp16 mma m16n8k16, fp32 accum.
// CTA tile 128x256, BK=64, 8 warps (2M x 4N), warp tile 64x64.
// 3-stage cp.async ring, SW128 swizzle, intra-kt fragment double buffer.
// Grid = 2 x 64 = 128 CTAs = one wave.
// ---------------------------------------------------------------------------
#define BM   128
#define BN   256
#define BK   64
#define NS   3
#define KT   (KDIM / BK)            /* 64 */
#define ASTG (BM * 128)             /* 16384 B */
#define BSTG (BN * 128)             /* 32768 B */
#define STG  (ASTG + BSTG)          /* 49152 B */

#define CP16(dst, src) \
    asm volatile("cp.async.cg.shared.global [%0], [%1], 16;\n" \
                 :: "r"(dst), "l"(src))

#define SWZ(o) ((o) ^ (((o) >> 3) & 0x70))

__device__ __forceinline__ void ldsm4(uint32_t& r0, uint32_t& r1,
                                      uint32_t& r2, uint32_t& r3,
                                      uint32_t addr) {
    asm volatile("ldmatrix.sync.aligned.m8n8.x4.shared.b16 {%0,%1,%2,%3}, [%4];\n"
                 : "=r"(r0), "=r"(r1), "=r"(r2), "=r"(r3) : "r"(addr));
}

__global__ void __launch_bounds__(256, 1)
gemm_kernel(float* __restrict__ out) {
    extern __shared__ __align__(1024) char smem[];

    const int tid  = threadIdx.x;
    const int warp = tid >> 5, lane = tid & 31;
    const int wn  = warp & 3;          // 4 N-warps
    const int wm2 = warp >> 2;         // 2 M-warps
    const int m0 = blockIdx.y * BM;
    const int n0 = blockIdx.x * BN;
    const uint32_t smem_base = (uint32_t)__cvta_generic_to_shared(smem);

    const int lr = lane & 15;
    const int lh = lane >> 4;

    float acc[4][8][4];
#pragma unroll
    for (int i = 0; i < 4; i++)
#pragma unroll
        for (int j = 0; j < 8; j++)
#pragma unroll
            for (int l = 0; l < 4; l++) acc[i][j][l] = 0.0f;

    // ---- stage loader: 16B cp.async chunks into SW128 smem ----
    auto load_stage = [&](int kt) {
        int slot = kt % NS;
        uint32_t sA = smem_base + slot * STG;
        uint32_t sB = sA + ASTG;
        int koff = kt * BK;
#pragma unroll
        for (int i = 0; i < 4; i++) {
            int idx = tid + i * 256;
            int row = idx >> 3, seg = idx & 7;
            const __half* src = g_Sh + (size_t)(m0 + row) * KDIM + koff + seg * 8;
            uint32_t off = row * 128 + seg * 16;
            CP16(sA + SWZ(off), src);
        }
#pragma unroll
        for (int i = 0; i < 8; i++) {
            int idx = tid + i * 256;
            int row = idx >> 3, seg = idx & 7;
            const __half* src = g_Bh + (size_t)(n0 + row) * KDIM + koff + seg * 8;
            uint32_t off = row * 128 + seg * 16;
            CP16(sB + SWZ(off), src);
        }
    };

    // fragment loader for one k-step (16 columns of the 64-wide stage)
    auto load_frags = [&](uint32_t sA, uint32_t sB, int ks,
                          uint32_t a[4][4], uint32_t b[4][4]) {
#pragma unroll
        for (int mf = 0; mf < 4; mf++) {
            int row = wm2 * 64 + mf * 16 + lr;
            uint32_t off = row * 128 + ks * 32 + lh * 16;
            ldsm4(a[mf][0], a[mf][1], a[mf][2], a[mf][3], sA + SWZ(off));
        }
#pragma unroll
        for (int p = 0; p < 4; p++) {
            int row = wn * 64 + p * 16 + lr;
            uint32_t off = row * 128 + ks * 32 + lh * 16;
            ldsm4(b[p][0], b[p][1], b[p][2], b[p][3], sB + SWZ(off));
        }
    };

    // prologue: stages 0..NS-2
#pragma unroll
    for (int s = 0; s < NS - 1; s++) {
        load_stage(s);
        asm volatile("cp.async.commit_group;" ::: "memory");
    }

    uint32_t afrag[2][4][4], bfrag[2][4][4];

    for (int kt = 0; kt < KT; kt++) {
        if (kt == KT - 1) asm volatile("cp.async.wait_group 0;" ::: "memory");
        else              asm volatile("cp.async.wait_group 1;" ::: "memory");
        __syncthreads();

        if (kt + NS - 1 < KT) {
            load_stage(kt + NS - 1);
            asm volatile("cp.async.commit_group;" ::: "memory");
        }

        int slot = kt % NS;
        uint32_t sA = smem_base + slot * STG;
        uint32_t sB = sA + ASTG;

        load_frags(sA, sB, 0, afrag[0], bfrag[0]);

#pragma unroll
        for (int ks = 0; ks < 4; ks++) {
            int cur = ks & 1, nxt = cur ^ 1;
            if (ks < 3) load_frags(sA, sB, ks + 1, afrag[nxt], bfrag[nxt]);
#pragma unroll
            for (int mf = 0; mf < 4; mf++)
#pragma unroll
                for (int nf = 0; nf < 8; nf++) {
                    int p = nf >> 1, hi = nf & 1;
                    uint32_t b0 = hi ? bfrag[cur][p][1] : bfrag[cur][p][0];
                    uint32_t b1 = hi ? bfrag[cur][p][3] : bfrag[cur][p][2];
                    asm volatile(
                        "mma.sync.aligned.m16n8k16.row.col.f32.f16.f16.f32 "
                        "{%0,%1,%2,%3}, {%4,%5,%6,%7}, {%8,%9}, {%0,%1,%2,%3};\n"
                        : "+f"(acc[mf][nf][0]), "+f"(acc[mf][nf][1]),
                          "+f"(acc[mf][nf][2]), "+f"(acc[mf][nf][3])
                        : "r"(afrag[cur][mf][0]), "r"(afrag[cur][mf][1]),
                          "r"(afrag[cur][mf][2]), "r"(afrag[cur][mf][3]),
                          "r"(b0), "r"(b1));
                }
        }
    }

    // epilogue: c0=(m,2t) c1=(m,2t+1) c2=(m+8,2t) c3=(m+8,2t+1)
    int gid = lane >> 2, tig = lane & 3;
#pragma unroll
    for (int mf = 0; mf < 4; mf++) {
        int m = m0 + wm2 * 64 + mf * 16 + gid;
#pragma unroll
        for (int nf = 0; nf < 8; nf++) {
            int n = n0 + wn * 64 + nf * 8 + tig * 2;
            *(float2*)(out + (size_t)m * OUT_SIZE + n) =
                make_float2(acc[mf][nf][0], acc[mf][nf][1]);
            *(float2*)(out + (size_t)(m + 8) * OUT_SIZE + n) =
                make_float2(acc[mf][nf][2], acc[mf][nf][3]);
        }
    }
}

// ---------------------------------------------------------------------------
extern "C" void kernel_launch(void* const* d_in, const int* in_sizes, int n_in,
                              void* d_out, int out_size) {
    const float* x    = (const float*)d_in[0];
    const float* w    = (const float*)d_in[1];
    const float* coef = (const float*)d_in[2];
    float* out = (float*)d_out;

    cudaFuncSetAttribute(gemm_kernel,
                         cudaFuncAttributeMaxDynamicSharedMemorySize,
                         NS * STG);

    prep_kernel<<<FOLD_BLOCKS + BASIS_BLOCKS, 256>>>(x, w, coef);
    gemm_kernel<<<dim3(OUT_SIZE / BN, BATCH / BM), 256, NS * STG>>>(out);
}

// round 16
// speedup vs baseline: 3.4891x; 1.0308x over previous
#include <cuda_runtime.h>
#include <cuda_fp16.h>
#include <cstdint>

#define BATCH    8192
#define IN_SIZE  512
#define OUT_SIZE 512
#define KDIM     4096

// Scratch (allocation-free rule: __device__ globals)
__device__ __half g_Sh[(size_t)BATCH * KDIM];     // basis, [M][K] row-major, fp16
__device__ __half g_Bh[(size_t)OUT_SIZE * KDIM];  // coeff*w, [N][K] row-major, fp16

#define FOLD_BLOCKS 1024                           /* 512*512/256 */
#define BASIS_BLOCKS 16384                         /* 8192*512/256 */

// ---------------------------------------------------------------------------
// Kernel 1: merged prep — fold (blocks [0,1024)) + basis (blocks [1024,...))
// ---------------------------------------------------------------------------
__global__ void prep_kernel(const float* __restrict__ x,
                            const float* __restrict__ w,
                            const float* __restrict__ coef) {
    if (blockIdx.x < FOLD_BLOCKS) {
        // fold: coeff*weight -> fp16, [N][K]
        int idx = blockIdx.x * blockDim.x + threadIdx.x;   // o*512 + i
        float wv = w[idx];
        const float4* c = (const float4*)(coef + (size_t)idx * 8);
        float4 c0 = c[0], c1 = c[1];
        __half2 h[4];
        h[0] = __floats2half2_rn(c0.x * wv, c0.y * wv);
        h[1] = __floats2half2_rn(c0.z * wv, c0.w * wv);
        h[2] = __floats2half2_rn(c1.x * wv, c1.y * wv);
        h[3] = __floats2half2_rn(c1.z * wv, c1.w * wv);
        *(uint4*)(g_Bh + (size_t)idx * 8) = *(uint4*)h;
    } else {
        // basis: De Boor cubic B-spline -> fp16
        int idx = (blockIdx.x - FOLD_BLOCKS) * blockDim.x + threadIdx.x;
        float xe = fminf(fmaxf(x[idx], -1.0f), 1.0f);

        const float start = -1.0f;
        const float stop  = 2.142857142857143f;
        const float step  = (stop - start) / 11.0f;

        float c[12];
#pragma unroll
        for (int k = 0; k < 12; k++) c[k] = start + (float)k * step;

        float b[11];
#pragma unroll
        for (int m = 0; m < 11; m++)
            b[m] = (xe >= c[m] && xe < c[m + 1]) ? 1.0f : 0.0f;

#pragma unroll
        for (int k = 1; k <= 3; k++) {
            float inv = 1.0f / ((float)k * step);
#pragma unroll
            for (int m = 0; m < 11 - k; m++)
                b[m] = ((xe - c[m]) * b[m] + (c[m + k + 1] - xe) * b[m + 1]) * inv;
        }

        __half2 h[4];
        h[0] = __floats2half2_rn(b[0], b[1]);
        h[1] = __floats2half2_rn(b[2], b[3]);
        h[2] = __floats2half2_rn(b[4], b[5]);
        h[3] = __floats2half2_rn(b[6], b[7]);
        *(uint4*)(g_Sh + (size_t)idx * 8) = *(uint4*)h;
    }
}

// ---------------------------------------------------------------------------
// Kernel 2: GEMM out[8192,512] = S[8192,4096] @ Bh[512,4096]^T
// fp16 mma m16n8k16, fp32 accum.
// CTA tile 128x128, BK=64, 8 warps (2M x 4N), warp tile 64x32.
// 3-stage cp.async ring (96 KB) -> 2 CTAs/SM (16 warps/SM, 4/SMSP) for
// cross-CTA latency/barrier coverage. Grid = 4 x 64 = 256 CTAs.
// ---------------------------------------------------------------------------
#define BM   128
#define BN   128
#define BK   64
#define NS   3
#define KT   (KDIM / BK)            /* 64 */
#define ASTG (BM * 128)             /* 16384 B */
#define BSTG (BN * 128)             /* 16384 B */
#define STG  (ASTG + BSTG)          /* 32768 B */

#define CP16(dst, src) \
    asm volatile("cp.async.cg.shared.global [%0], [%1], 16;\n" \
                 :: "r"(dst), "l"(src))

#define SWZ(o) ((o) ^ (((o) >> 3) & 0x70))

__device__ __forceinline__ void ldsm4(uint32_t& r0, uint32_t& r1,
                                      uint32_t& r2, uint32_t& r3,
                                      uint32_t addr) {
    asm volatile("ldmatrix.sync.aligned.m8n8.x4.shared.b16 {%0,%1,%2,%3}, [%4];\n"
                 : "=r"(r0), "=r"(r1), "=r"(r2), "=r"(r3) : "r"(addr));
}

__global__ void __launch_bounds__(256, 2)
gemm_kernel(float* __restrict__ out) {
    extern __shared__ __align__(1024) char smem[];

    const int tid  = threadIdx.x;
    const int warp = tid >> 5, lane = tid & 31;
    const int wn  = warp & 3;          // 4 N-warps (32 cols each)
    const int wm2 = warp >> 2;         // 2 M-warps (64 rows each)
    const int m0 = blockIdx.y * BM;
    const int n0 = blockIdx.x * BN;
    const uint32_t smem_base = (uint32_t)__cvta_generic_to_shared(smem);

    const int lr = lane & 15;
    const int lh = lane >> 4;

    float acc[4][4][4];
#pragma unroll
    for (int i = 0; i < 4; i++)
#pragma unroll
        for (int j = 0; j < 4; j++)
#pragma unroll
            for (int l = 0; l < 4; l++) acc[i][j][l] = 0.0f;

    // ---- stage loader: 16B cp.async chunks into SW128 smem ----
    auto load_stage = [&](int kt) {
        int slot = kt % NS;
        uint32_t sA = smem_base + slot * STG;
        uint32_t sB = sA + ASTG;
        int koff = kt * BK;
        // A: 128 rows x 8 segs = 1024 chunks, 4/thread
#pragma unroll
        for (int i = 0; i < 4; i++) {
            int idx = tid + i * 256;
            int row = idx >> 3, seg = idx & 7;
            const __half* src = g_Sh + (size_t)(m0 + row) * KDIM + koff + seg * 8;
            uint32_t off = row * 128 + seg * 16;
            CP16(sA + SWZ(off), src);
        }
        // B: 128 rows x 8 segs = 1024 chunks, 4/thread
#pragma unroll
        for (int i = 0; i < 4; i++) {
            int idx = tid + i * 256;
            int row = idx >> 3, seg = idx & 7;
            const __half* src = g_Bh + (size_t)(n0 + row) * KDIM + koff + seg * 8;
            uint32_t off = row * 128 + seg * 16;
            CP16(sB + SWZ(off), src);
        }
    };

    // prologue: stages 0..NS-2
#pragma unroll
    for (int s = 0; s < NS - 1; s++) {
        load_stage(s);
        asm volatile("cp.async.commit_group;" ::: "memory");
    }

    for (int kt = 0; kt < KT; kt++) {
        if (kt == KT - 1) asm volatile("cp.async.wait_group 0;" ::: "memory");
        else              asm volatile("cp.async.wait_group 1;" ::: "memory");
        __syncthreads();

        if (kt + NS - 1 < KT) {
            load_stage(kt + NS - 1);
            asm volatile("cp.async.commit_group;" ::: "memory");
        }

        int slot = kt % NS;
        uint32_t sA = smem_base + slot * STG;
        uint32_t sB = sA + ASTG;

#pragma unroll
        for (int ks = 0; ks < 4; ks++) {
            uint32_t a[4][4], b[2][4];
#pragma unroll
            for (int mf = 0; mf < 4; mf++) {
                int row = wm2 * 64 + mf * 16 + lr;
                uint32_t off = row * 128 + ks * 32 + lh * 16;
                ldsm4(a[mf][0], a[mf][1], a[mf][2], a[mf][3], sA + SWZ(off));
            }
#pragma unroll
            for (int p = 0; p < 2; p++) {
                int row = wn * 32 + p * 16 + lr;
                uint32_t off = row * 128 + ks * 32 + lh * 16;
                ldsm4(b[p][0], b[p][1], b[p][2], b[p][3], sB + SWZ(off));
            }
#pragma unroll
            for (int mf = 0; mf < 4; mf++)
#pragma unroll
                for (int nf = 0; nf < 4; nf++) {
                    int p = nf >> 1, hi = nf & 1;
                    uint32_t b0 = hi ? b[p][1] : b[p][0];
                    uint32_t b1 = hi ? b[p][3] : b[p][2];
                    asm volatile(
                        "mma.sync.aligned.m16n8k16.row.col.f32.f16.f16.f32 "
                        "{%0,%1,%2,%3}, {%4,%5,%6,%7}, {%8,%9}, {%0,%1,%2,%3};\n"
                        : "+f"(acc[mf][nf][0]), "+f"(acc[mf][nf][1]),
                          "+f"(acc[mf][nf][2]), "+f"(acc[mf][nf][3])
                        : "r"(a[mf][0]), "r"(a[mf][1]),
                          "r"(a[mf][2]), "r"(a[mf][3]),
                          "r"(b0), "r"(b1));
                }
        }
    }

    // epilogue: c0=(m,2t) c1=(m,2t+1) c2=(m+8,2t) c3=(m+8,2t+1)
    int gid = lane >> 2, tig = lane & 3;
#pragma unroll
    for (int mf = 0; mf < 4; mf++) {
        int m = m0 + wm2 * 64 + mf * 16 + gid;
#pragma unroll
        for (int nf = 0; nf < 4; nf++) {
            int n = n0 + wn * 32 + nf * 8 + tig * 2;
            *(float2*)(out + (size_t)m * OUT_SIZE + n) =
                make_float2(acc[mf][nf][0], acc[mf][nf][1]);
            *(float2*)(out + (size_t)(m + 8) * OUT_SIZE + n) =
                make_float2(acc[mf][nf][2], acc[mf][nf][3]);
        }
    }
}

// ---------------------------------------------------------------------------
extern "C" void kernel_launch(void* const* d_in, const int* in_sizes, int n_in,
                              void* d_out, int out_size) {
    const float* x    = (const float*)d_in[0];
    const float* w    = (const float*)d_in[1];
    const float* coef = (const float*)d_in[2];
    float* out = (float*)d_out;

    cudaFuncSetAttribute(gemm_kernel,
                         cudaFuncAttributeMaxDynamicSharedMemorySize,
                         NS * STG);

    prep_kernel<<<FOLD_BLOCKS + BASIS_BLOCKS, 256>>>(x, w, coef);
    gemm_kernel<<<dim3(OUT_SIZE / BN, BATCH / BM), 256, NS * STG>>>(out);
}